// round 12
// baseline (speedup 1.0000x reference)
#include <cuda_runtime.h>
#include <math.h>

// Problem constants
#define BB   64      // batch
#define NN   512     // nodes
#define RR   64      // r' (RP)
#define FEATD 256    // node features
#define EMBD 128     // embedding
#define TT   8       // MAX_WALK_LEN
#define D0   512     // MLP width (RR*TT)

#define LOG2E 1.4426950408889634f

// ---------------------------------------------------------------------------
// Device scratch (no cudaMalloc allowed)
// ---------------------------------------------------------------------------
__device__ float        g_M[RR * FEATD];             // Wv @ W  [64,256]
__device__ float        g_F1[BB * RR * NN];          // F1      [B,64,512]
__device__ float        g_FnA[BB * RR * NN];         // ping
__device__ float        g_FnB[BB * RR * NN];         // pong
__device__ unsigned int g_adjp[BB * NN * (NN / 32)]; // packed adjacency bits [B][m][n/32]
__device__ float        g_gpart[BB * TT * 2 * RR];   // gate partials per (b,t,tile,r)

// ---------------------------------------------------------------------------
// K0: pack adjacency: bit n of g_adjp[b][m][w] = (adj[b][n][m] != 0), n = w*32+j
// ---------------------------------------------------------------------------
__global__ void k_pack_adj(const int* __restrict__ adj) {
    int b  = blockIdx.y;
    int w  = blockIdx.x & 15;
    int mt = blockIdx.x >> 4;
    int m  = mt * 256 + threadIdx.x;
    const int* base = adj + ((size_t)b * NN + w * 32) * NN + m;
    unsigned int word = 0;
#pragma unroll
    for (int j = 0; j < 32; j++)
        word |= (base[j * NN] != 0 ? 1u : 0u) << j;
    g_adjp[(b * NN + m) * (NN / 32) + w] = word;
}

// ---------------------------------------------------------------------------
// K1: M = Wv[64,128] @ W[128,256]
// ---------------------------------------------------------------------------
__global__ void k_M(const float* __restrict__ Wv, const float* __restrict__ W) {
    int idx = blockIdx.x * 256 + threadIdx.x;
    int r = idx >> 8, c = idx & 255;
    float a = 0.f;
#pragma unroll 4
    for (int e = 0; e < EMBD; e++)
        a += Wv[r * EMBD + e] * W[e * FEATD + c];
    g_M[r * FEATD + c] = a;
}

// ---------------------------------------------------------------------------
// K2: F1[b,:,m] = sigmoid(M @ attr[b,m,:]) ; also gate_0 partials
// grid (2, 64), block 256, one column per thread
// ---------------------------------------------------------------------------
#define SM_F1 ((RR * FEATD + RR * RR + 8 * RR) * 4)

__global__ void __launch_bounds__(256, 1)
k_F1(const float* __restrict__ attr, const float* __restrict__ Wg) {
    extern __shared__ float sm[];
    float* smM  = sm;                   // [64][256]
    float* smWg = sm + RR * FEATD;      // [64][64]
    float* smG  = smWg + RR * RR;       // [8][64]

    int b = blockIdx.y, tile = blockIdx.x, tid = threadIdx.x;

    {
        const float4* s = (const float4*)g_M;
        float4* d = (float4*)smM;
        for (int i = tid; i < RR * FEATD / 4; i += 256) d[i] = s[i];
        const float4* s2 = (const float4*)Wg;
        float4* d2 = (float4*)smWg;
        for (int i = tid; i < RR * RR / 4; i += 256) d2[i] = s2[i];
    }
    __syncthreads();

    int m = tile * 256 + tid;
    float acc[RR];
#pragma unroll
    for (int r = 0; r < RR; r++) acc[r] = 0.f;

    const float4* arow = (const float4*)(attr + ((size_t)b * NN + m) * FEATD);
#pragma unroll 1
    for (int k4 = 0; k4 < FEATD / 4; k4++) {
        float4 a = __ldg(&arow[k4]);
        const float4* mc = (const float4*)smM + k4;
#pragma unroll
        for (int r = 0; r < RR; r++) {
            float4 w = mc[r * (FEATD / 4)];
            acc[r] += a.x * w.x + a.y * w.y + a.z * w.z + a.w * w.w;
        }
    }

#pragma unroll
    for (int r = 0; r < RR; r++) {
        float v = 1.f / (1.f + __expf(-acc[r]));
        acc[r] = v;
        g_F1[((size_t)b * RR + r) * NN + m] = v;
    }

    int lane = tid & 31, wrp = tid >> 5;
#pragma unroll 1
    for (int r = 0; r < RR; r++) {
        const float4* wr = (const float4*)(smWg + r * RR);
        float g = 0.f;
#pragma unroll
        for (int s4 = 0; s4 < RR / 4; s4++) {
            float4 w = wr[s4];
            g += w.x * acc[s4 * 4] + w.y * acc[s4 * 4 + 1] +
                 w.z * acc[s4 * 4 + 2] + w.w * acc[s4 * 4 + 3];
        }
        g = 1.f / (1.f + __expf(-g));
#pragma unroll
        for (int o = 16; o > 0; o >>= 1) g += __shfl_xor_sync(0xffffffffu, g, o);
        if (lane == 0) smG[wrp * RR + r] = g;
    }
    __syncthreads();
    if (tid < RR) {
        float tot = 0.f;
#pragma unroll
        for (int w = 0; w < 8; w++) tot += smG[w * RR + tid];
        g_gpart[((b * TT + 0) * 2 + tile) * RR + tid] = tot;
    }
}

// ---------------------------------------------------------------------------
// K3: one walk iteration (masked attention) + gate  [R11 core + SW pipeline]
// grid (2, 64), block 512. Two threads per column: thread s owns interleaved
// rows r = s + 2i (i < 32). Row stride 520 (== 8 mod 32): conflict-free
// broadcast LDS. 8 keys per chunk; score pass packed fma.rn.f32x2; acc scalar.
// Direct exp via ex2.approx with log2(e) folded into wwf.
// SOFTWARE PIPELINE: score pass of chunk k+1 is issued between the shfl-
// combine of chunk k and its ex2/acc consumers, hiding the serial
// shfl(26)+ex2(16) chain inside each warp.
// ---------------------------------------------------------------------------
#define RSTRIDE 520
#define WSTRIDE 72
#define SM_ITER ((64 * RSTRIDE + 64 * WSTRIDE + RR * RR + 16 * RR) * 4 + 256 * 16 * 4)

__global__ void __launch_bounds__(512, 1)
k_iter(const float* __restrict__ Ww, const float* __restrict__ Wg, int t) {
    extern __shared__ float sm[];
    float*        smFnP = sm;                                // [64][520]
    float*        smWwP = sm + 64 * RSTRIDE;                 // [sp][72] permuted
    float*        smWg  = smWwP + 64 * WSTRIDE;              // [r][s]
    unsigned int* smAdj = (unsigned int*)(smWg + RR * RR);   // [256][16]
    float*        smG   = (float*)(smAdj + 256 * 16);        // [16][64]

    int b = blockIdx.y, tile = blockIdx.x, tid = threadIdx.x;

    const float* Fn_in  = (t == 1) ? g_F1 : ((t & 1) ? g_FnB : g_FnA);
    float*       Fn_out = (t & 1) ? g_FnA : g_FnB;

    {
        const float4* src = (const float4*)(Fn_in + (size_t)b * RR * NN);
        for (int idx = tid; idx < RR * NN / 4; idx += 512) {
            int row = idx >> 7, c4 = idx & 127;
            *((float4*)(smFnP + row * RSTRIDE) + c4) = src[idx];
        }
        // permuted Ww for interleaved slices: smWwP[sp*72 + (r&1)*36 + (r>>1)] = Ww[r][sp]
        for (int i = tid; i < RR * RR; i += 512) {
            int r = i >> 6, sp = i & 63;
            smWwP[sp * WSTRIDE + (r & 1) * 36 + (r >> 1)] = Ww[i];
        }
        const float4* s3 = (const float4*)Wg;
        float4* d3 = (float4*)smWg;
        for (int i = tid; i < RR * RR / 4; i += 512) d3[i] = s3[i];
        const uint4* s4p = (const uint4*)(g_adjp + ((size_t)b * NN + tile * 256) * 16);
        uint4* d4 = (uint4*)smAdj;
        for (int i = tid; i < 256 * 16 / 4; i += 512) d4[i] = s4p[i];
    }
    __syncthreads();

    int s  = tid & 1;          // slice: rows r = s + 2i
    int ml = tid >> 1;         // local column 0..255
    int m  = tile * 256 + ml;

    // ---- wwf[i] = sum_s' Ww[s+2i][s'] * Fn[s'][m], then fold in log2(e)
    float wwf[32];
#pragma unroll
    for (int i = 0; i < 32; i++) wwf[i] = 0.f;
#pragma unroll 1
    for (int sp = 0; sp < 64; sp++) {
        float fs = smFnP[sp * RSTRIDE + m];
        const float4* wq = (const float4*)(smWwP + sp * WSTRIDE + s * 36);
#pragma unroll
        for (int q = 0; q < 8; q++) {
            float4 w = wq[q];
            wwf[q*4+0] += w.x * fs;
            wwf[q*4+1] += w.y * fs;
            wwf[q*4+2] += w.z * fs;
            wwf[q*4+3] += w.w * fs;
        }
    }
#pragma unroll
    for (int i = 0; i < 32; i++) wwf[i] *= LOG2E;   // ex2(S*log2e) == e^S

    // score pass for one 8-key chunk (partial, this slice) — packed f32x2
    auto score8 = [&](const ulonglong2* fr, unsigned long long& a01,
                      unsigned long long& a23, unsigned long long& a45,
                      unsigned long long& a67) {
#pragma unroll
        for (int i = 0; i < 32; i++) {
            ulonglong2 fa = fr[i * 260];       // keys n0..n3
            ulonglong2 fb = fr[i * 260 + 1];   // keys n4..n7
            unsigned long long w2;
            asm("mov.b64 %0, {%1, %1};" : "=l"(w2) : "f"(wwf[i]));
            asm("fma.rn.f32x2 %0, %1, %2, %0;" : "+l"(a01) : "l"(fa.x), "l"(w2));
            asm("fma.rn.f32x2 %0, %1, %2, %0;" : "+l"(a23) : "l"(fa.y), "l"(w2));
            asm("fma.rn.f32x2 %0, %1, %2, %0;" : "+l"(a45) : "l"(fb.x), "l"(w2));
            asm("fma.rn.f32x2 %0, %1, %2, %0;" : "+l"(a67) : "l"(fb.y), "l"(w2));
        }
    };

    // ---- masked attention, 8 keys per chunk, direct ex2, SW-pipelined
    float acc[32];
#pragma unroll
    for (int i = 0; i < 32; i++) acc[i] = 0.f;
    float dn = 0.f;
    const unsigned int* myadj = smAdj + ml * 16;
    const ulonglong2* frows = (const ulonglong2*)(smFnP + s * RSTRIDE);

    unsigned int aw = myadj[0];
    unsigned long long c01 = 0ull, c23 = 0ull, c45 = 0ull, c67 = 0ull;
    score8(frows, c01, c23, c45, c67);   // prologue: chunk 0 scores

#pragma unroll 1
    for (int n0 = 0; n0 < NN - 8; n0 += 8) {
        if ((n0 & 31) == 0) aw = myadj[n0 >> 5];

        // shfl-combine current chunk (starts the serial chain)
        unsigned long long o0 = __shfl_xor_sync(0xffffffffu, c01, 1);
        unsigned long long o1 = __shfl_xor_sync(0xffffffffu, c23, 1);
        unsigned long long o2 = __shfl_xor_sync(0xffffffffu, c45, 1);
        unsigned long long o3 = __shfl_xor_sync(0xffffffffu, c67, 1);
        asm("add.rn.f32x2 %0, %0, %1;" : "+l"(c01) : "l"(o0));
        asm("add.rn.f32x2 %0, %0, %1;" : "+l"(c23) : "l"(o1));
        asm("add.rn.f32x2 %0, %0, %1;" : "+l"(c45) : "l"(o2));
        asm("add.rn.f32x2 %0, %0, %1;" : "+l"(c67) : "l"(o3));

        // score pass of NEXT chunk — independent work to hide shfl/ex2 latency
        unsigned long long t01 = 0ull, t23 = 0ull, t45 = 0ull, t67 = 0ull;
        score8(frows + ((n0 + 8) >> 2), t01, t23, t45, t67);

        // finalize current chunk: unpack, ex2, mask, denom
        float s0, s1, s2, s3, s4, s5, s6, s7;
        asm("mov.b64 {%0, %1}, %2;" : "=f"(s0), "=f"(s1) : "l"(c01));
        asm("mov.b64 {%0, %1}, %2;" : "=f"(s2), "=f"(s3) : "l"(c23));
        asm("mov.b64 {%0, %1}, %2;" : "=f"(s4), "=f"(s5) : "l"(c45));
        asm("mov.b64 {%0, %1}, %2;" : "=f"(s6), "=f"(s7) : "l"(c67));

        unsigned int bits = aw >> (n0 & 31);
        float e0, e1, e2, e3, e4, e5, e6, e7;
        asm("ex2.approx.f32 %0, %1;" : "=f"(e0) : "f"(s0));
        asm("ex2.approx.f32 %0, %1;" : "=f"(e1) : "f"(s1));
        asm("ex2.approx.f32 %0, %1;" : "=f"(e2) : "f"(s2));
        asm("ex2.approx.f32 %0, %1;" : "=f"(e3) : "f"(s3));
        asm("ex2.approx.f32 %0, %1;" : "=f"(e4) : "f"(s4));
        asm("ex2.approx.f32 %0, %1;" : "=f"(e5) : "f"(s5));
        asm("ex2.approx.f32 %0, %1;" : "=f"(e6) : "f"(s6));
        asm("ex2.approx.f32 %0, %1;" : "=f"(e7) : "f"(s7));
        float p0 = (bits & 1u)   ? e0 : 0.f;
        float p1 = (bits & 2u)   ? e1 : 0.f;
        float p2 = (bits & 4u)   ? e2 : 0.f;
        float p3 = (bits & 8u)   ? e3 : 0.f;
        float p4 = (bits & 16u)  ? e4 : 0.f;
        float p5 = (bits & 32u)  ? e5 : 0.f;
        float p6 = (bits & 64u)  ? e6 : 0.f;
        float p7 = (bits & 128u) ? e7 : 0.f;
        dn += ((p0 + p1) + (p2 + p3)) + ((p4 + p5) + (p6 + p7));

        // acc pass for current chunk
#pragma unroll
        for (int i = 0; i < 32; i++) {
            const float4* row = (const float4*)(smFnP + (s + 2*i) * RSTRIDE + n0);
            float4 a = row[0], b4 = row[1];
            acc[i] += a.x * p0 + a.y * p1 + a.z * p2 + a.w * p3 +
                      b4.x * p4 + b4.y * p5 + b4.z * p6 + b4.w * p7;
        }

        // rotate pipeline
        c01 = t01; c23 = t23; c45 = t45; c67 = t67;
    }

    // epilogue: finalize last chunk (n0 = 504; aw = myadj[15] from n0=480)
    {
        const int n0 = NN - 8;
        unsigned long long o0 = __shfl_xor_sync(0xffffffffu, c01, 1);
        unsigned long long o1 = __shfl_xor_sync(0xffffffffu, c23, 1);
        unsigned long long o2 = __shfl_xor_sync(0xffffffffu, c45, 1);
        unsigned long long o3 = __shfl_xor_sync(0xffffffffu, c67, 1);
        asm("add.rn.f32x2 %0, %0, %1;" : "+l"(c01) : "l"(o0));
        asm("add.rn.f32x2 %0, %0, %1;" : "+l"(c23) : "l"(o1));
        asm("add.rn.f32x2 %0, %0, %1;" : "+l"(c45) : "l"(o2));
        asm("add.rn.f32x2 %0, %0, %1;" : "+l"(c67) : "l"(o3));

        float s0, s1, s2, s3, s4, s5, s6, s7;
        asm("mov.b64 {%0, %1}, %2;" : "=f"(s0), "=f"(s1) : "l"(c01));
        asm("mov.b64 {%0, %1}, %2;" : "=f"(s2), "=f"(s3) : "l"(c23));
        asm("mov.b64 {%0, %1}, %2;" : "=f"(s4), "=f"(s5) : "l"(c45));
        asm("mov.b64 {%0, %1}, %2;" : "=f"(s6), "=f"(s7) : "l"(c67));

        unsigned int bits = aw >> (n0 & 31);
        float e0, e1, e2, e3, e4, e5, e6, e7;
        asm("ex2.approx.f32 %0, %1;" : "=f"(e0) : "f"(s0));
        asm("ex2.approx.f32 %0, %1;" : "=f"(e1) : "f"(s1));
        asm("ex2.approx.f32 %0, %1;" : "=f"(e2) : "f"(s2));
        asm("ex2.approx.f32 %0, %1;" : "=f"(e3) : "f"(s3));
        asm("ex2.approx.f32 %0, %1;" : "=f"(e4) : "f"(s4));
        asm("ex2.approx.f32 %0, %1;" : "=f"(e5) : "f"(s5));
        asm("ex2.approx.f32 %0, %1;" : "=f"(e6) : "f"(s6));
        asm("ex2.approx.f32 %0, %1;" : "=f"(e7) : "f"(s7));
        float p0 = (bits & 1u)   ? e0 : 0.f;
        float p1 = (bits & 2u)   ? e1 : 0.f;
        float p2 = (bits & 4u)   ? e2 : 0.f;
        float p3 = (bits & 8u)   ? e3 : 0.f;
        float p4 = (bits & 16u)  ? e4 : 0.f;
        float p5 = (bits & 32u)  ? e5 : 0.f;
        float p6 = (bits & 64u)  ? e6 : 0.f;
        float p7 = (bits & 128u) ? e7 : 0.f;
        dn += ((p0 + p1) + (p2 + p3)) + ((p4 + p5) + (p6 + p7));

#pragma unroll
        for (int i = 0; i < 32; i++) {
            const float4* row = (const float4*)(smFnP + (s + 2*i) * RSTRIDE + n0);
            float4 a = row[0], b4 = row[1];
            acc[i] += a.x * p0 + a.y * p1 + a.z * p2 + a.w * p3 +
                      b4.x * p4 + b4.y * p5 + b4.z * p6 + b4.w * p7;
        }
    }

    // ---- epilogue: scale, multiply by F1, write global + restage to smem
    float inv = 1.f / dn;
    __syncthreads();   // all reads of old smFnP complete before restaging
    const float* f1base = g_F1 + (size_t)b * RR * NN;
    float*       outb   = Fn_out + (size_t)b * RR * NN;
#pragma unroll
    for (int i = 0; i < 32; i++) {
        int r = s + 2 * i;
        float v = acc[i] * inv * f1base[r * NN + m];
        outb[r * NN + m] = v;
        smFnP[r * RSTRIDE + ml] = v;
    }
    __syncthreads();

    // ---- gate_t = sum_m sigmoid(Wg @ Fn_new[:,m])  (validated structure)
    int rb = (tid & 1) * 32;      // r-half for the gate dot
    float f[32];
#pragma unroll
    for (int i = 0; i < 32; i++) f[i] = smFnP[(rb + i) * RSTRIDE + ml];

    int lane = tid & 31, wrp = tid >> 5;
#pragma unroll 1
    for (int r = 0; r < RR; r++) {
        const float4* wr = (const float4*)(smWg + r * RR + rb);
        float g = 0.f;
#pragma unroll
        for (int s4 = 0; s4 < 8; s4++) {
            float4 w = wr[s4];
            g += w.x * f[s4*4] + w.y * f[s4*4+1] +
                 w.z * f[s4*4+2] + w.w * f[s4*4+3];
        }
        g += __shfl_xor_sync(0xffffffffu, g, 1);       // full dot for this column
        g = 1.f / (1.f + __expf(-g));
#pragma unroll
        for (int o = 2; o < 32; o <<= 1) g += __shfl_xor_sync(0xffffffffu, g, o);
        if (lane == 0) smG[wrp * RR + r] = g;          // 16 distinct columns per warp
    }
    __syncthreads();
    if (tid < RR) {
        float tot = 0.f;
#pragma unroll
        for (int w = 0; w < 16; w++) tot += smG[w * RR + tid];
        g_gpart[((b * TT + t) * 2 + tile) * RR + tid] = tot;
    }
}

// ---------------------------------------------------------------------------
// K4: assemble fT, L2-normalize, 4-layer MLP. grid 16 (4 batches/CTA), block 256
// ---------------------------------------------------------------------------
__device__ __forceinline__ void mlp_layer(const float (*hin)[D0], float (*hout)[D0],
                                          const float* __restrict__ W,
                                          const float* __restrict__ bias,
                                          int Din, int Dout, int tid) {
    for (int i = tid; i < Dout; i += 256) {
        const float4* wr = (const float4*)(W + (size_t)i * Din);
        float a0 = 0.f, a1 = 0.f, a2 = 0.f, a3 = 0.f;
#pragma unroll 4
        for (int k4 = 0; k4 < Din / 4; k4++) {
            float4 w = __ldg(&wr[k4]);
            float4 x0 = *(const float4*)&hin[0][k4 * 4];
            float4 x1 = *(const float4*)&hin[1][k4 * 4];
            float4 x2 = *(const float4*)&hin[2][k4 * 4];
            float4 x3 = *(const float4*)&hin[3][k4 * 4];
            a0 += w.x * x0.x + w.y * x0.y + w.z * x0.z + w.w * x0.w;
            a1 += w.x * x1.x + w.y * x1.y + w.z * x1.z + w.w * x1.w;
            a2 += w.x * x2.x + w.y * x2.y + w.z * x2.z + w.w * x2.w;
            a3 += w.x * x3.x + w.y * x3.y + w.z * x3.z + w.w * x3.w;
        }
        float bi = bias[i];
        hout[0][i] = fmaxf(a0 + bi, 0.f);
        hout[1][i] = fmaxf(a1 + bi, 0.f);
        hout[2][i] = fmaxf(a2 + bi, 0.f);
        hout[3][i] = fmaxf(a3 + bi, 0.f);
    }
}

__global__ void __launch_bounds__(256, 1)
k_mlp(const float* __restrict__ W0, const float* __restrict__ b0,
      const float* __restrict__ W1, const float* __restrict__ b1,
      const float* __restrict__ W2, const float* __restrict__ b2,
      const float* __restrict__ W3, const float* __restrict__ b3,
      float* __restrict__ out) {
    __shared__ float hA[4][D0];
    __shared__ float hB[4][D0];
    __shared__ float smScale[4];
    int tid = threadIdx.x;
    int bbase = blockIdx.x * 4;

    for (int idx = tid; idx < 4 * D0; idx += 256) {
        int bb = idx >> 9, j = idx & 511, t = j >> 6, r = j & 63;
        int g0 = (((bbase + bb) * TT + t) * 2 + 0) * RR + r;
        hA[bb][j] = g_gpart[g0] + g_gpart[g0 + RR];
    }
    __syncthreads();

    int lane = tid & 31, wrp = tid >> 5;
    if (wrp < 4) {
        float ss = 0.f;
        for (int i = lane; i < D0; i += 32) { float v = hA[wrp][i]; ss += v * v; }
#pragma unroll
        for (int o = 16; o > 0; o >>= 1) ss += __shfl_xor_sync(0xffffffffu, ss, o);
        if (lane == 0) smScale[wrp] = 1.f / fmaxf(sqrtf(ss), 1e-12f);
    }
    __syncthreads();
    for (int idx = tid; idx < 4 * D0; idx += 256) {
        int bb = idx >> 9;
        hA[bb][idx & 511] *= smScale[bb];
    }
    __syncthreads();

    mlp_layer(hA, hB, W0, b0, 512, 512, tid); __syncthreads();
    mlp_layer(hB, hA, W1, b1, 512, 512, tid); __syncthreads();
    mlp_layer(hA, hB, W2, b2, 512, 256, tid); __syncthreads();

    for (int i = tid; i < 128; i += 256) {
        const float4* wr = (const float4*)(W3 + (size_t)i * 256);
        float a0 = 0.f, a1 = 0.f, a2 = 0.f, a3 = 0.f;
#pragma unroll 4
        for (int k4 = 0; k4 < 64; k4++) {
            float4 w = __ldg(&wr[k4]);
            float4 x0 = *(const float4*)&hB[0][k4 * 4];
            float4 x1 = *(const float4*)&hB[1][k4 * 4];
            float4 x2 = *(const float4*)&hB[2][k4 * 4];
            float4 x3 = *(const float4*)&hB[3][k4 * 4];
            a0 += w.x * x0.x + w.y * x0.y + w.z * x0.z + w.w * x0.w;
            a1 += w.x * x1.x + w.y * x1.y + w.z * x1.z + w.w * x1.w;
            a2 += w.x * x2.x + w.y * x2.y + w.z * x2.z + w.w * x2.w;
            a3 += w.x * x3.x + w.y * x3.y + w.z * x3.z + w.w * x3.w;
        }
        float bi = b3[i];
        out[(bbase + 0) * 128 + i] = a0 + bi;
        out[(bbase + 1) * 128 + i] = a1 + bi;
        out[(bbase + 2) * 128 + i] = a2 + bi;
        out[(bbase + 3) * 128 + i] = a3 + bi;
    }
}

// ---------------------------------------------------------------------------
// launch
// ---------------------------------------------------------------------------
extern "C" void kernel_launch(void* const* d_in, const int* in_sizes, int n_in,
                              void* d_out, int out_size) {
    const float* attr = (const float*)d_in[0];
    const int*   adj  = (const int*)d_in[1];
    const float* W    = (const float*)d_in[2];
    const float* Wv   = (const float*)d_in[3];
    const float* Ww   = (const float*)d_in[4];
    const float* Wg   = (const float*)d_in[5];
    const float* W0   = (const float*)d_in[6];
    const float* b0   = (const float*)d_in[7];
    const float* W1   = (const float*)d_in[8];
    const float* b1   = (const float*)d_in[9];
    const float* W2   = (const float*)d_in[10];
    const float* b2   = (const float*)d_in[11];
    const float* W3   = (const float*)d_in[12];
    const float* b3   = (const float*)d_in[13];
    float* out = (float*)d_out;

    cudaFuncSetAttribute(k_F1,   cudaFuncAttributeMaxDynamicSharedMemorySize, SM_F1);
    cudaFuncSetAttribute(k_iter, cudaFuncAttributeMaxDynamicSharedMemorySize, SM_ITER);

    k_pack_adj<<<dim3(32, 64), 256>>>(adj);
    k_M<<<64, 256>>>(Wv, W);
    k_F1<<<dim3(2, 64), 256, SM_F1>>>(attr, Wg);
    for (int t = 1; t < TT; t++)
        k_iter<<<dim3(2, 64), 512, SM_ITER>>>(Ww, Wg, t);
    k_mlp<<<16, 256>>>(W0, b0, W1, b1, W2, b2, W3, b3, out);
}

// round 15
// speedup vs baseline: 1.0779x; 1.0779x over previous
#include <cuda_runtime.h>
#include <math.h>

// Problem constants
#define BB   64      // batch
#define NN   512     // nodes
#define RR   64      // r' (RP)
#define FEATD 256    // node features
#define EMBD 128     // embedding
#define TT   8       // MAX_WALK_LEN
#define D0   512     // MLP width (RR*TT)

#define LOG2E 1.4426950408889634f

typedef unsigned long long ull;

// ---------------------------------------------------------------------------
// Device scratch (no cudaMalloc allowed)
// ---------------------------------------------------------------------------
__device__ float        g_M[RR * FEATD];             // Wv @ W  [64,256]
__device__ float        g_F1[BB * RR * NN];          // F1      [B,64,512]
__device__ float        g_FnA[BB * RR * NN];         // ping
__device__ float        g_FnB[BB * RR * NN];         // pong
__device__ unsigned int g_adjp[BB * NN * (NN / 32)]; // packed adjacency bits [B][m][n/32]
__device__ float        g_gpart[BB * TT * 2 * RR];   // gate partials per (b,t,tile,r)

// ---------------------------------------------------------------------------
// K0: pack adjacency: bit n of g_adjp[b][m][w] = (adj[b][n][m] != 0), n = w*32+j
// ---------------------------------------------------------------------------
__global__ void k_pack_adj(const int* __restrict__ adj) {
    int b  = blockIdx.y;
    int w  = blockIdx.x & 15;
    int mt = blockIdx.x >> 4;
    int m  = mt * 256 + threadIdx.x;
    const int* base = adj + ((size_t)b * NN + w * 32) * NN + m;
    unsigned int word = 0;
#pragma unroll
    for (int j = 0; j < 32; j++)
        word |= (base[j * NN] != 0 ? 1u : 0u) << j;
    g_adjp[(b * NN + m) * (NN / 32) + w] = word;
}

// ---------------------------------------------------------------------------
// K1: M = Wv[64,128] @ W[128,256]
// ---------------------------------------------------------------------------
__global__ void k_M(const float* __restrict__ Wv, const float* __restrict__ W) {
    int idx = blockIdx.x * 256 + threadIdx.x;
    int r = idx >> 8, c = idx & 255;
    float a = 0.f;
#pragma unroll 4
    for (int e = 0; e < EMBD; e++)
        a += Wv[r * EMBD + e] * W[e * FEATD + c];
    g_M[r * FEATD + c] = a;
}

// ---------------------------------------------------------------------------
// K2: F1[b,:,m] = sigmoid(M @ attr[b,m,:]) ; also gate_0 partials
// grid (2, 64), block 256, one column per thread
// ---------------------------------------------------------------------------
#define SM_F1 ((RR * FEATD + RR * RR + 8 * RR) * 4)

__global__ void __launch_bounds__(256, 1)
k_F1(const float* __restrict__ attr, const float* __restrict__ Wg) {
    extern __shared__ float sm[];
    float* smM  = sm;                   // [64][256]
    float* smWg = sm + RR * FEATD;      // [64][64]
    float* smG  = smWg + RR * RR;       // [8][64]

    int b = blockIdx.y, tile = blockIdx.x, tid = threadIdx.x;

    {
        const float4* s = (const float4*)g_M;
        float4* d = (float4*)smM;
        for (int i = tid; i < RR * FEATD / 4; i += 256) d[i] = s[i];
        const float4* s2 = (const float4*)Wg;
        float4* d2 = (float4*)smWg;
        for (int i = tid; i < RR * RR / 4; i += 256) d2[i] = s2[i];
    }
    __syncthreads();

    int m = tile * 256 + tid;
    float acc[RR];
#pragma unroll
    for (int r = 0; r < RR; r++) acc[r] = 0.f;

    const float4* arow = (const float4*)(attr + ((size_t)b * NN + m) * FEATD);
#pragma unroll 1
    for (int k4 = 0; k4 < FEATD / 4; k4++) {
        float4 a = __ldg(&arow[k4]);
        const float4* mc = (const float4*)smM + k4;
#pragma unroll
        for (int r = 0; r < RR; r++) {
            float4 w = mc[r * (FEATD / 4)];
            acc[r] += a.x * w.x + a.y * w.y + a.z * w.z + a.w * w.w;
        }
    }

#pragma unroll
    for (int r = 0; r < RR; r++) {
        float v = 1.f / (1.f + __expf(-acc[r]));
        acc[r] = v;
        g_F1[((size_t)b * RR + r) * NN + m] = v;
    }

    int lane = tid & 31, wrp = tid >> 5;
#pragma unroll 1
    for (int r = 0; r < RR; r++) {
        const float4* wr = (const float4*)(smWg + r * RR);
        float g = 0.f;
#pragma unroll
        for (int s4 = 0; s4 < RR / 4; s4++) {
            float4 w = wr[s4];
            g += w.x * acc[s4 * 4] + w.y * acc[s4 * 4 + 1] +
                 w.z * acc[s4 * 4 + 2] + w.w * acc[s4 * 4 + 3];
        }
        g = 1.f / (1.f + __expf(-g));
#pragma unroll
        for (int o = 16; o > 0; o >>= 1) g += __shfl_xor_sync(0xffffffffu, g, o);
        if (lane == 0) smG[wrp * RR + r] = g;
    }
    __syncthreads();
    if (tid < RR) {
        float tot = 0.f;
#pragma unroll
        for (int w = 0; w < 8; w++) tot += smG[w * RR + tid];
        g_gpart[((b * TT + 0) * 2 + tile) * RR + tid] = tot;
    }
}

// ---------------------------------------------------------------------------
// K3: one walk iteration (masked attention) + gate  [exact R11 main loop]
// grid (2, 64), block 512. Two threads per column: thread s owns interleaved
// rows r = s + 2i (i < 32). Row stride 520 (== 8 mod 32): conflict-free
// broadcast LDS. 8 keys per chunk; score pass packed fma.rn.f32x2; acc scalar.
// Direct exp via ex2.approx with log2(e) folded into wwf.
// Gate dot packed as FFMA2 (post-loop, register-pressure-free).
// ---------------------------------------------------------------------------
#define RSTRIDE 520
#define WSTRIDE 72
#define SM_ITER ((64 * RSTRIDE + 64 * WSTRIDE + RR * RR + 16 * RR) * 4 + 256 * 16 * 4)

__global__ void __launch_bounds__(512, 1)
k_iter(const float* __restrict__ Ww, const float* __restrict__ Wg, int t) {
    extern __shared__ float sm[];
    float*        smFnP = sm;                                // [64][520]
    float*        smWwP = sm + 64 * RSTRIDE;                 // [sp][72] permuted
    float*        smWg  = smWwP + 64 * WSTRIDE;              // [r][s]
    unsigned int* smAdj = (unsigned int*)(smWg + RR * RR);   // [256][16]
    float*        smG   = (float*)(smAdj + 256 * 16);        // [16][64]

    int b = blockIdx.y, tile = blockIdx.x, tid = threadIdx.x;

    const float* Fn_in  = (t == 1) ? g_F1 : ((t & 1) ? g_FnB : g_FnA);
    float*       Fn_out = (t & 1) ? g_FnA : g_FnB;

    {
        const float4* src = (const float4*)(Fn_in + (size_t)b * RR * NN);
        for (int idx = tid; idx < RR * NN / 4; idx += 512) {
            int row = idx >> 7, c4 = idx & 127;
            *((float4*)(smFnP + row * RSTRIDE) + c4) = src[idx];
        }
        // permuted Ww for interleaved slices: smWwP[sp*72 + (r&1)*36 + (r>>1)] = Ww[r][sp]
        for (int i = tid; i < RR * RR; i += 512) {
            int r = i >> 6, sp = i & 63;
            smWwP[sp * WSTRIDE + (r & 1) * 36 + (r >> 1)] = Ww[i];
        }
        const float4* s3 = (const float4*)Wg;
        float4* d3 = (float4*)smWg;
        for (int i = tid; i < RR * RR / 4; i += 512) d3[i] = s3[i];
        const uint4* s4p = (const uint4*)(g_adjp + ((size_t)b * NN + tile * 256) * 16);
        uint4* d4 = (uint4*)smAdj;
        for (int i = tid; i < 256 * 16 / 4; i += 512) d4[i] = s4p[i];
    }
    __syncthreads();

    int s  = tid & 1;          // slice: rows r = s + 2i
    int ml = tid >> 1;         // local column 0..255
    int m  = tile * 256 + ml;

    // ---- wwf[i] = sum_s' Ww[s+2i][s'] * Fn[s'][m], then fold in log2(e)
    float wwf[32];
#pragma unroll
    for (int i = 0; i < 32; i++) wwf[i] = 0.f;
#pragma unroll 1
    for (int sp = 0; sp < 64; sp++) {
        float fs = smFnP[sp * RSTRIDE + m];
        const float4* wq = (const float4*)(smWwP + sp * WSTRIDE + s * 36);
#pragma unroll
        for (int q = 0; q < 8; q++) {
            float4 w = wq[q];
            wwf[q*4+0] += w.x * fs;
            wwf[q*4+1] += w.y * fs;
            wwf[q*4+2] += w.z * fs;
            wwf[q*4+3] += w.w * fs;
        }
    }
#pragma unroll
    for (int i = 0; i < 32; i++) wwf[i] *= LOG2E;   // ex2(S*log2e) == e^S

    // ---- masked attention, 8 keys per chunk, direct ex2  [exact R11 loop]
    float acc[32];
#pragma unroll
    for (int i = 0; i < 32; i++) acc[i] = 0.f;
    float dn = 0.f;
    unsigned int aw = 0;
    const unsigned int* myadj = smAdj + ml * 16;
    const ulonglong2* frows = (const ulonglong2*)(smFnP + s * RSTRIDE);

#pragma unroll 1
    for (int n0 = 0; n0 < NN; n0 += 8) {
        if ((n0 & 31) == 0) aw = myadj[n0 >> 5];

        const ulonglong2* fr = frows + (n0 >> 2);   // rows s+2i step 260 ul2

        // packed partial scores for this slice: s01, s23, s45, s67
        unsigned long long s01 = 0ull, s23 = 0ull, s45 = 0ull, s67 = 0ull;
#pragma unroll
        for (int i = 0; i < 32; i++) {
            ulonglong2 fa = fr[i * 260];       // keys n0..n3
            ulonglong2 fb = fr[i * 260 + 1];   // keys n4..n7
            unsigned long long w2;
            asm("mov.b64 %0, {%1, %1};" : "=l"(w2) : "f"(wwf[i]));
            asm("fma.rn.f32x2 %0, %1, %2, %0;" : "+l"(s01) : "l"(fa.x), "l"(w2));
            asm("fma.rn.f32x2 %0, %1, %2, %0;" : "+l"(s23) : "l"(fa.y), "l"(w2));
            asm("fma.rn.f32x2 %0, %1, %2, %0;" : "+l"(s45) : "l"(fb.x), "l"(w2));
            asm("fma.rn.f32x2 %0, %1, %2, %0;" : "+l"(s67) : "l"(fb.y), "l"(w2));
        }
        // combine with pair partner (other slice) — batched for ILP
        {
            unsigned long long o0 = __shfl_xor_sync(0xffffffffu, s01, 1);
            unsigned long long o1 = __shfl_xor_sync(0xffffffffu, s23, 1);
            unsigned long long o2 = __shfl_xor_sync(0xffffffffu, s45, 1);
            unsigned long long o3 = __shfl_xor_sync(0xffffffffu, s67, 1);
            asm("add.rn.f32x2 %0, %0, %1;" : "+l"(s01) : "l"(o0));
            asm("add.rn.f32x2 %0, %0, %1;" : "+l"(s23) : "l"(o1));
            asm("add.rn.f32x2 %0, %0, %1;" : "+l"(s45) : "l"(o2));
            asm("add.rn.f32x2 %0, %0, %1;" : "+l"(s67) : "l"(o3));
        }
        float s0, s1, s2, s3, s4, s5, s6, s7;
        asm("mov.b64 {%0, %1}, %2;" : "=f"(s0), "=f"(s1) : "l"(s01));
        asm("mov.b64 {%0, %1}, %2;" : "=f"(s2), "=f"(s3) : "l"(s23));
        asm("mov.b64 {%0, %1}, %2;" : "=f"(s4), "=f"(s5) : "l"(s45));
        asm("mov.b64 {%0, %1}, %2;" : "=f"(s6), "=f"(s7) : "l"(s67));

        unsigned int bits = aw >> (n0 & 31);
        float e0, e1, e2, e3, e4, e5, e6, e7;
        asm("ex2.approx.f32 %0, %1;" : "=f"(e0) : "f"(s0));
        asm("ex2.approx.f32 %0, %1;" : "=f"(e1) : "f"(s1));
        asm("ex2.approx.f32 %0, %1;" : "=f"(e2) : "f"(s2));
        asm("ex2.approx.f32 %0, %1;" : "=f"(e3) : "f"(s3));
        asm("ex2.approx.f32 %0, %1;" : "=f"(e4) : "f"(s4));
        asm("ex2.approx.f32 %0, %1;" : "=f"(e5) : "f"(s5));
        asm("ex2.approx.f32 %0, %1;" : "=f"(e6) : "f"(s6));
        asm("ex2.approx.f32 %0, %1;" : "=f"(e7) : "f"(s7));
        float p0 = (bits & 1u)   ? e0 : 0.f;
        float p1 = (bits & 2u)   ? e1 : 0.f;
        float p2 = (bits & 4u)   ? e2 : 0.f;
        float p3 = (bits & 8u)   ? e3 : 0.f;
        float p4 = (bits & 16u)  ? e4 : 0.f;
        float p5 = (bits & 32u)  ? e5 : 0.f;
        float p6 = (bits & 64u)  ? e6 : 0.f;
        float p7 = (bits & 128u) ? e7 : 0.f;
        dn += ((p0 + p1) + (p2 + p3)) + ((p4 + p5) + (p6 + p7));

#pragma unroll
        for (int i = 0; i < 32; i++) {
            const float4* row = (const float4*)(smFnP + (s + 2*i) * RSTRIDE + n0);
            float4 a = row[0], b4 = row[1];
            acc[i] += a.x * p0 + a.y * p1 + a.z * p2 + a.w * p3 +
                      b4.x * p4 + b4.y * p5 + b4.z * p6 + b4.w * p7;
        }
    }

    // ---- epilogue: scale, multiply by F1, write global + restage to smem
    float inv = 1.f / dn;
    __syncthreads();   // all reads of old smFnP complete before restaging
    const float* f1base = g_F1 + (size_t)b * RR * NN;
    float*       outb   = Fn_out + (size_t)b * RR * NN;
#pragma unroll
    for (int i = 0; i < 32; i++) {
        int r = s + 2 * i;
        float v = acc[i] * inv * f1base[r * NN + m];
        outb[r * NN + m] = v;
        smFnP[r * RSTRIDE + ml] = v;
    }
    __syncthreads();

    // ---- gate_t = sum_m sigmoid(Wg @ Fn_new[:,m]) — packed FFMA2 dot
    int rb = (tid & 1) * 32;      // r-half for the gate dot
    float f[32];
#pragma unroll
    for (int i = 0; i < 32; i++) f[i] = smFnP[(rb + i) * RSTRIDE + ml];
    ull fp[16];                   // (f[2q], f[2q+1]) packed; rows rb+2q, rb+2q+1
#pragma unroll
    for (int q = 0; q < 16; q++)
        asm("mov.b64 %0, {%1, %2};" : "=l"(fp[q]) : "f"(f[2*q]), "f"(f[2*q+1]));

    int lane = tid & 31, wrp = tid >> 5;
#pragma unroll 1
    for (int r = 0; r < RR; r++) {
        const ulonglong2* wr = (const ulonglong2*)(smWg + r * RR + rb);
        ull g2 = 0ull;
#pragma unroll
        for (int q4 = 0; q4 < 8; q4++) {
            ulonglong2 w = wr[q4];
            asm("fma.rn.f32x2 %0, %1, %2, %0;" : "+l"(g2) : "l"(w.x), "l"(fp[2*q4]));
            asm("fma.rn.f32x2 %0, %1, %2, %0;" : "+l"(g2) : "l"(w.y), "l"(fp[2*q4+1]));
        }
        float glo, ghi;
        asm("mov.b64 {%0, %1}, %2;" : "=f"(glo), "=f"(ghi) : "l"(g2));
        float g = glo + ghi;
        g += __shfl_xor_sync(0xffffffffu, g, 1);       // full dot for this column
        g = 1.f / (1.f + __expf(-g));
#pragma unroll
        for (int o = 2; o < 32; o <<= 1) g += __shfl_xor_sync(0xffffffffu, g, o);
        if (lane == 0) smG[wrp * RR + r] = g;          // 16 distinct columns per warp
    }
    __syncthreads();
    if (tid < RR) {
        float tot = 0.f;
#pragma unroll
        for (int w = 0; w < 16; w++) tot += smG[w * RR + tid];
        g_gpart[((b * TT + t) * 2 + tile) * RR + tid] = tot;
    }
}

// ---------------------------------------------------------------------------
// K4: assemble fT, L2-normalize, 4-layer MLP. grid 16 (4 batches/CTA), block 512
// ---------------------------------------------------------------------------
__device__ __forceinline__ void mlp_layer(const float (*hin)[D0], float (*hout)[D0],
                                          const float* __restrict__ W,
                                          const float* __restrict__ bias,
                                          int Din, int Dout, int tid) {
    for (int i = tid; i < Dout; i += 512) {
        const float4* wr = (const float4*)(W + (size_t)i * Din);
        float a0 = 0.f, a1 = 0.f, a2 = 0.f, a3 = 0.f;
#pragma unroll 4
        for (int k4 = 0; k4 < Din / 4; k4++) {
            float4 w = __ldg(&wr[k4]);
            float4 x0 = *(const float4*)&hin[0][k4 * 4];
            float4 x1 = *(const float4*)&hin[1][k4 * 4];
            float4 x2 = *(const float4*)&hin[2][k4 * 4];
            float4 x3 = *(const float4*)&hin[3][k4 * 4];
            a0 += w.x * x0.x + w.y * x0.y + w.z * x0.z + w.w * x0.w;
            a1 += w.x * x1.x + w.y * x1.y + w.z * x1.z + w.w * x1.w;
            a2 += w.x * x2.x + w.y * x2.y + w.z * x2.z + w.w * x2.w;
            a3 += w.x * x3.x + w.y * x3.y + w.z * x3.z + w.w * x3.w;
        }
        float bi = bias[i];
        hout[0][i] = fmaxf(a0 + bi, 0.f);
        hout[1][i] = fmaxf(a1 + bi, 0.f);
        hout[2][i] = fmaxf(a2 + bi, 0.f);
        hout[3][i] = fmaxf(a3 + bi, 0.f);
    }
}

__global__ void __launch_bounds__(512, 1)
k_mlp(const float* __restrict__ W0, const float* __restrict__ b0,
      const float* __restrict__ W1, const float* __restrict__ b1,
      const float* __restrict__ W2, const float* __restrict__ b2,
      const float* __restrict__ W3, const float* __restrict__ b3,
      float* __restrict__ out) {
    __shared__ float hA[4][D0];
    __shared__ float hB[4][D0];
    __shared__ float smScale[4];
    int tid = threadIdx.x;
    int bbase = blockIdx.x * 4;

    for (int idx = tid; idx < 4 * D0; idx += 512) {
        int bb = idx >> 9, j = idx & 511, t = j >> 6, r = j & 63;
        int g0 = (((bbase + bb) * TT + t) * 2 + 0) * RR + r;
        hA[bb][j] = g_gpart[g0] + g_gpart[g0 + RR];
    }
    __syncthreads();

    int lane = tid & 31, wrp = tid >> 5;
    if (wrp < 4) {
        float ss = 0.f;
        for (int i = lane; i < D0; i += 32) { float v = hA[wrp][i]; ss += v * v; }
#pragma unroll
        for (int o = 16; o > 0; o >>= 1) ss += __shfl_xor_sync(0xffffffffu, ss, o);
        if (lane == 0) smScale[wrp] = 1.f / fmaxf(sqrtf(ss), 1e-12f);
    }
    __syncthreads();
    for (int idx = tid; idx < 4 * D0; idx += 512) {
        int bb = idx >> 9;
        hA[bb][idx & 511] *= smScale[bb];
    }
    __syncthreads();

    mlp_layer(hA, hB, W0, b0, 512, 512, tid); __syncthreads();
    mlp_layer(hB, hA, W1, b1, 512, 512, tid); __syncthreads();
    mlp_layer(hA, hB, W2, b2, 512, 256, tid); __syncthreads();

    for (int i = tid; i < 128; i += 512) {
        const float4* wr = (const float4*)(W3 + (size_t)i * 256);
        float a0 = 0.f, a1 = 0.f, a2 = 0.f, a3 = 0.f;
#pragma unroll 4
        for (int k4 = 0; k4 < 64; k4++) {
            float4 w = __ldg(&wr[k4]);
            float4 x0 = *(const float4*)&hB[0][k4 * 4];
            float4 x1 = *(const float4*)&hB[1][k4 * 4];
            float4 x2 = *(const float4*)&hB[2][k4 * 4];
            float4 x3 = *(const float4*)&hB[3][k4 * 4];
            a0 += w.x * x0.x + w.y * x0.y + w.z * x0.z + w.w * x0.w;
            a1 += w.x * x1.x + w.y * x1.y + w.z * x1.z + w.w * x1.w;
            a2 += w.x * x2.x + w.y * x2.y + w.z * x2.z + w.w * x2.w;
            a3 += w.x * x3.x + w.y * x3.y + w.z * x3.z + w.w * x3.w;
        }
        float bi = b3[i];
        out[(bbase + 0) * 128 + i] = a0 + bi;
        out[(bbase + 1) * 128 + i] = a1 + bi;
        out[(bbase + 2) * 128 + i] = a2 + bi;
        out[(bbase + 3) * 128 + i] = a3 + bi;
    }
}

// ---------------------------------------------------------------------------
// launch
// ---------------------------------------------------------------------------
extern "C" void kernel_launch(void* const* d_in, const int* in_sizes, int n_in,
                              void* d_out, int out_size) {
    const float* attr = (const float*)d_in[0];
    const int*   adj  = (const int*)d_in[1];
    const float* W    = (const float*)d_in[2];
    const float* Wv   = (const float*)d_in[3];
    const float* Ww   = (const float*)d_in[4];
    const float* Wg   = (const float*)d_in[5];
    const float* W0   = (const float*)d_in[6];
    const float* b0   = (const float*)d_in[7];
    const float* W1   = (const float*)d_in[8];
    const float* b1   = (const float*)d_in[9];
    const float* W2   = (const float*)d_in[10];
    const float* b2   = (const float*)d_in[11];
    const float* W3   = (const float*)d_in[12];
    const float* b3   = (const float*)d_in[13];
    float* out = (float*)d_out;

    cudaFuncSetAttribute(k_F1,   cudaFuncAttributeMaxDynamicSharedMemorySize, SM_F1);
    cudaFuncSetAttribute(k_iter, cudaFuncAttributeMaxDynamicSharedMemorySize, SM_ITER);

    k_pack_adj<<<dim3(32, 64), 256>>>(adj);
    k_M<<<64, 256>>>(Wv, W);
    k_F1<<<dim3(2, 64), 256, SM_F1>>>(attr, Wg);
    for (int t = 1; t < TT; t++)
        k_iter<<<dim3(2, 64), 512, SM_ITER>>>(Ww, Wg, t);
    k_mlp<<<16, 512>>>(W0, b0, W1, b1, W2, b2, W3, b3, out);
}